// round 6
// baseline (speedup 1.0000x reference)
#include <cuda_runtime.h>

// ---------------------------------------------------------------------------
// 3-layer GCN:  (deg/dinv/norm prep)  ->  [GEMM -> scatter -> bias/relu]x3
//               -> log_softmax
// N=100000 nodes, E=3200000 edges, F_IN=64, HID=16, C=4
//
// R6 fix: NEVER pass __device__ globals as host-side kernel arguments (nvcc
// silently passes the host shadow address -> scatter writes vanished ->
// near-constant output, rel_err 0.0427 = sigma_ref/log(4) exactly).
// Scatter kernels now reference their globals from device code.
// Edge layout: planar int32 [src(0..E); dst(E..2E)] (natural numpy C-order,
// confirmed by R2 OOB crash signature).
// ---------------------------------------------------------------------------

#define NN 100000
#define NE 3200000
#define FIN 64
#define HID 16
#define NC 4
#define TPB 256

__device__ float g_dinv[NN];                       // deg -> dinv (in place)
__device__ int   g_row[NE];
__device__ int   g_col[NE];
__device__ float g_norm[NE];
__device__ __align__(16) float g_h1[NN * HID];
__device__ __align__(16) float g_agg1[NN * HID];
__device__ __align__(16) float g_h2[NN * HID];
__device__ __align__(16) float g_agg2[NN * HID];
__device__ __align__(16) float g_h3[NN * NC];
__device__ __align__(16) float g_agg3[NN * NC];

__device__ __forceinline__ int clampN(int v) {
    v = v < 0 ? 0 : v;
    return v >= NN ? NN - 1 : v;
}

// --------------------------- graph prep ------------------------------------

__global__ void k_init_deg() {
    int i = blockIdx.x * TPB + threadIdx.x;
    if (i < NN) g_dinv[i] = 1.0f;   // self-loop weight
}

__global__ void k_edge_prep(const int* __restrict__ ei,
                            const float* __restrict__ ew) {
    int e = blockIdx.x * TPB + threadIdx.x;
    if (e >= NE) return;
    int r = clampN(ei[e]);          // edge_index[0][e] : source
    int c = clampN(ei[NE + e]);     // edge_index[1][e] : target
    g_row[e] = r;
    g_col[e] = c;
    atomicAdd(&g_dinv[c], ew[e]);
}

__global__ void k_rsqrt() {
    int i = blockIdx.x * TPB + threadIdx.x;
    if (i >= NN) return;
    float d = g_dinv[i];
    g_dinv[i] = (d > 0.0f) ? rsqrtf(d) : 0.0f;
}

__global__ void k_norm(const float* __restrict__ ew) {
    int e = blockIdx.x * TPB + threadIdx.x;
    if (e >= NE) return;
    g_norm[e] = g_dinv[g_row[e]] * ew[e] * g_dinv[g_col[e]];
}

// --------------------------- layer 1: x @ W1 -------------------------------
// h1 = x @ W1 ; agg1 initialized with the self-loop term dinv^2 * h1.

__global__ void k_gemm1(const float* __restrict__ x,
                        const float* __restrict__ W1) {
    __shared__ float Ws[FIN * HID];
    for (int t = threadIdx.x; t < FIN * HID; t += TPB) Ws[t] = W1[t];
    __syncthreads();

    int i = blockIdx.x * TPB + threadIdx.x;
    if (i >= NN) return;

    float acc[HID];
#pragma unroll
    for (int j = 0; j < HID; j++) acc[j] = 0.0f;

    const float4* xr = (const float4*)(x + (size_t)i * FIN);
#pragma unroll
    for (int k4 = 0; k4 < FIN / 4; k4++) {
        float4 xv = xr[k4];
#pragma unroll
        for (int j = 0; j < HID; j++) {
            acc[j] += xv.x * Ws[(k4 * 4 + 0) * HID + j];
            acc[j] += xv.y * Ws[(k4 * 4 + 1) * HID + j];
            acc[j] += xv.z * Ws[(k4 * 4 + 2) * HID + j];
            acc[j] += xv.w * Ws[(k4 * 4 + 3) * HID + j];
        }
    }

    float di = g_dinv[i];
    float dd = di * di;
    float4* h = (float4*)(g_h1 + i * HID);
    float4* a = (float4*)(g_agg1 + i * HID);
#pragma unroll
    for (int j4 = 0; j4 < HID / 4; j4++) {
        float4 v = make_float4(acc[j4 * 4 + 0], acc[j4 * 4 + 1],
                               acc[j4 * 4 + 2], acc[j4 * 4 + 3]);
        h[j4] = v;
        a[j4] = make_float4(dd * v.x, dd * v.y, dd * v.z, dd * v.w);
    }
}

// --------------------------- scatters (HID=16) -----------------------------
// Device-side references to the globals only — no host-passed symbol addrs.

__global__ void k_scatter16_l1() {
    int e = blockIdx.x * TPB + threadIdx.x;
    if (e >= NE) return;
    int r = g_row[e];
    int c = g_col[e];
    float nm = g_norm[e];
    const float4* hr = (const float4*)(g_h1 + r * HID);
    float4* dst = (float4*)(g_agg1 + c * HID);
#pragma unroll
    for (int j4 = 0; j4 < HID / 4; j4++) {
        float4 v = hr[j4];
        atomicAdd(dst + j4, make_float4(nm * v.x, nm * v.y, nm * v.z, nm * v.w));
    }
}

__global__ void k_scatter16_l2() {
    int e = blockIdx.x * TPB + threadIdx.x;
    if (e >= NE) return;
    int r = g_row[e];
    int c = g_col[e];
    float nm = g_norm[e];
    const float4* hr = (const float4*)(g_h2 + r * HID);
    float4* dst = (float4*)(g_agg2 + c * HID);
#pragma unroll
    for (int j4 = 0; j4 < HID / 4; j4++) {
        float4 v = hr[j4];
        atomicAdd(dst + j4, make_float4(nm * v.x, nm * v.y, nm * v.z, nm * v.w));
    }
}

// ---------- finalize layer1 (bias+relu) + GEMM2 (16x16) + agg2 init --------

__global__ void k_fin1_gemm2(const float* __restrict__ b1,
                             const float* __restrict__ W3) {
    __shared__ float Ws[HID * HID];
    __shared__ float bs[HID];
    for (int t = threadIdx.x; t < HID * HID; t += TPB) Ws[t] = W3[t];
    if (threadIdx.x < HID) bs[threadIdx.x] = b1[threadIdx.x];
    __syncthreads();

    int i = blockIdx.x * TPB + threadIdx.x;
    if (i >= NN) return;

    float v[HID];
    const float4* ar = (const float4*)(g_agg1 + i * HID);
#pragma unroll
    for (int j4 = 0; j4 < HID / 4; j4++) {
        float4 a = ar[j4];
        v[j4 * 4 + 0] = fmaxf(a.x + bs[j4 * 4 + 0], 0.0f);
        v[j4 * 4 + 1] = fmaxf(a.y + bs[j4 * 4 + 1], 0.0f);
        v[j4 * 4 + 2] = fmaxf(a.z + bs[j4 * 4 + 2], 0.0f);
        v[j4 * 4 + 3] = fmaxf(a.w + bs[j4 * 4 + 3], 0.0f);
    }

    float acc[HID];
#pragma unroll
    for (int j = 0; j < HID; j++) acc[j] = 0.0f;
#pragma unroll
    for (int k = 0; k < HID; k++) {
        float vk = v[k];
#pragma unroll
        for (int j = 0; j < HID; j++) acc[j] += vk * Ws[k * HID + j];
    }

    float di = g_dinv[i];
    float dd = di * di;
    float4* h = (float4*)(g_h2 + i * HID);
    float4* a = (float4*)(g_agg2 + i * HID);
#pragma unroll
    for (int j4 = 0; j4 < HID / 4; j4++) {
        float4 w = make_float4(acc[j4 * 4 + 0], acc[j4 * 4 + 1],
                               acc[j4 * 4 + 2], acc[j4 * 4 + 3]);
        h[j4] = w;
        a[j4] = make_float4(dd * w.x, dd * w.y, dd * w.z, dd * w.w);
    }
}

// ---------- finalize layer2 (bias+relu) + GEMM3 (16x4) + agg3 init ---------

__global__ void k_fin2_gemm3(const float* __restrict__ b3,
                             const float* __restrict__ W2) {
    __shared__ float Ws[HID * NC];
    __shared__ float bs[HID];
    for (int t = threadIdx.x; t < HID * NC; t += TPB) Ws[t] = W2[t];
    if (threadIdx.x < HID) bs[threadIdx.x] = b3[threadIdx.x];
    __syncthreads();

    int i = blockIdx.x * TPB + threadIdx.x;
    if (i >= NN) return;

    float v[HID];
    const float4* ar = (const float4*)(g_agg2 + i * HID);
#pragma unroll
    for (int j4 = 0; j4 < HID / 4; j4++) {
        float4 a = ar[j4];
        v[j4 * 4 + 0] = fmaxf(a.x + bs[j4 * 4 + 0], 0.0f);
        v[j4 * 4 + 1] = fmaxf(a.y + bs[j4 * 4 + 1], 0.0f);
        v[j4 * 4 + 2] = fmaxf(a.z + bs[j4 * 4 + 2], 0.0f);
        v[j4 * 4 + 3] = fmaxf(a.w + bs[j4 * 4 + 3], 0.0f);
    }

    float acc[NC] = {0.0f, 0.0f, 0.0f, 0.0f};
#pragma unroll
    for (int k = 0; k < HID; k++) {
        float vk = v[k];
#pragma unroll
        for (int j = 0; j < NC; j++) acc[j] += vk * Ws[k * NC + j];
    }

    float di = g_dinv[i];
    float dd = di * di;
    float4 w = make_float4(acc[0], acc[1], acc[2], acc[3]);
    ((float4*)(g_h3 + i * NC))[0] = w;
    ((float4*)(g_agg3 + i * NC))[0] =
        make_float4(dd * w.x, dd * w.y, dd * w.z, dd * w.w);
}

// --------------------------- scatter (NC=4) --------------------------------

__global__ void k_scatter4() {
    int e = blockIdx.x * TPB + threadIdx.x;
    if (e >= NE) return;
    int r = g_row[e];
    int c = g_col[e];
    float nm = g_norm[e];
    float4 v = ((const float4*)(g_h3 + r * NC))[0];
    atomicAdd((float4*)(g_agg3 + c * NC),
              make_float4(nm * v.x, nm * v.y, nm * v.z, nm * v.w));
}

// --------------------------- bias + log_softmax ----------------------------

__global__ void k_logsoftmax(const float* __restrict__ b2,
                             float* __restrict__ out) {
    int i = blockIdx.x * TPB + threadIdx.x;
    if (i >= NN) return;
    float4 a = ((const float4*)(g_agg3 + i * NC))[0];
    float z0 = a.x + b2[0];
    float z1 = a.y + b2[1];
    float z2 = a.z + b2[2];
    float z3 = a.w + b2[3];
    float m = fmaxf(fmaxf(z0, z1), fmaxf(z2, z3));
    float s = expf(z0 - m) + expf(z1 - m) + expf(z2 - m) + expf(z3 - m);
    float lse = m + logf(s);
    float4 o = make_float4(z0 - lse, z1 - lse, z2 - lse, z3 - lse);
    ((float4*)(out + i * NC))[0] = o;
}

// ---------------------------------------------------------------------------

extern "C" void kernel_launch(void* const* d_in, const int* in_sizes, int n_in,
                              void* d_out, int out_size) {
    const float* x  = (const float*)d_in[0];
    const int*   ei = (const int*)d_in[1];
    const float* ew = (const float*)d_in[2];
    const float* W1 = (const float*)d_in[3];
    const float* b1 = (const float*)d_in[4];
    const float* W3 = (const float*)d_in[5];
    const float* b3 = (const float*)d_in[6];
    const float* W2 = (const float*)d_in[7];
    const float* b2 = (const float*)d_in[8];
    float* out = (float*)d_out;

    const int nbN = (NN + TPB - 1) / TPB;
    const int nbE = (NE + TPB - 1) / TPB;

    k_init_deg<<<nbN, TPB>>>();
    k_edge_prep<<<nbE, TPB>>>(ei, ew);
    k_rsqrt<<<nbN, TPB>>>();
    k_norm<<<nbE, TPB>>>(ew);

    k_gemm1<<<nbN, TPB>>>(x, W1);
    k_scatter16_l1<<<nbE, TPB>>>();

    k_fin1_gemm2<<<nbN, TPB>>>(b1, W3);
    k_scatter16_l2<<<nbE, TPB>>>();

    k_fin2_gemm3<<<nbN, TPB>>>(b3, W2);
    k_scatter4<<<nbE, TPB>>>();

    k_logsoftmax<<<nbN, TPB>>>(b2, out);
}

// round 7
// speedup vs baseline: 1.1239x; 1.1239x over previous
#include <cuda_runtime.h>

// ---------------------------------------------------------------------------
// 3-layer GCN, R7 optimization pass.
// Key algebra: norm[e]*h[row] = dinv[col] * ew[e] * (dinv[row]*h[row]).
// Store h' = dinv*h at each GEMM output; scatter accumulates ew*h'[row];
// finalize multiplies by dinv[col]. Self-loop handled by initializing
// agg = h' (ew_loop = 1). This deletes the norm/row/col scratch arrays and
// the k_norm kernel, and removes all per-edge dinv gathers.
// Scatters read edge_index (planar int32) + edge_weight directly, 2 edges
// per thread via int2/float2 loads.
// ---------------------------------------------------------------------------

#define NN 100000
#define NE 3200000
#define FIN 64
#define HID 16
#define NC 4
#define TPB 256

__device__ float g_dinv[NN];
__device__ __align__(16) float g_h1[NN * HID];   // h' = dinv * (x@W1)
__device__ __align__(16) float g_agg1[NN * HID];
__device__ __align__(16) float g_h2[NN * HID];
__device__ __align__(16) float g_agg2[NN * HID];
__device__ __align__(16) float g_h3[NN * NC];
__device__ __align__(16) float g_agg3[NN * NC];

__device__ __forceinline__ int clampN(int v) {
    v = v < 0 ? 0 : v;
    return v >= NN ? NN - 1 : v;
}

// --------------------------- graph prep ------------------------------------

__global__ void k_init_deg() {
    int i = blockIdx.x * TPB + threadIdx.x;
    if (i < NN) g_dinv[i] = 1.0f;   // self-loop weight
}

// deg[c] += ew  (only the target half of edge_index is needed)
__global__ void k_deg(const int* __restrict__ ei, const float* __restrict__ ew) {
    int t = blockIdx.x * TPB + threadIdx.x;
    int e = t * 2;
    if (e >= NE) return;
    int2   cc = *(const int2*)(ei + NE + e);
    float2 ww = *(const float2*)(ew + e);
    atomicAdd(&g_dinv[clampN(cc.x)], ww.x);
    atomicAdd(&g_dinv[clampN(cc.y)], ww.y);
}

__global__ void k_rsqrt() {
    int i = blockIdx.x * TPB + threadIdx.x;
    if (i >= NN) return;
    float d = g_dinv[i];
    g_dinv[i] = (d > 0.0f) ? rsqrtf(d) : 0.0f;
}

// ------------------- layer 1: h1' = dinv*(x@W1); agg1 = h1' ----------------

__global__ void k_gemm1(const float* __restrict__ x,
                        const float* __restrict__ W1) {
    __shared__ float Ws[FIN * HID];
    for (int t = threadIdx.x; t < FIN * HID; t += TPB) Ws[t] = W1[t];
    __syncthreads();

    int i = blockIdx.x * TPB + threadIdx.x;
    if (i >= NN) return;

    float acc[HID];
#pragma unroll
    for (int j = 0; j < HID; j++) acc[j] = 0.0f;

    const float4* xr = (const float4*)(x + (size_t)i * FIN);
#pragma unroll
    for (int k4 = 0; k4 < FIN / 4; k4++) {
        float4 xv = xr[k4];
#pragma unroll
        for (int j = 0; j < HID; j++) {
            acc[j] += xv.x * Ws[(k4 * 4 + 0) * HID + j];
            acc[j] += xv.y * Ws[(k4 * 4 + 1) * HID + j];
            acc[j] += xv.z * Ws[(k4 * 4 + 2) * HID + j];
            acc[j] += xv.w * Ws[(k4 * 4 + 3) * HID + j];
        }
    }

    float di = g_dinv[i];
    float4* h = (float4*)(g_h1 + i * HID);
    float4* a = (float4*)(g_agg1 + i * HID);
#pragma unroll
    for (int j4 = 0; j4 < HID / 4; j4++) {
        float4 v = make_float4(di * acc[j4 * 4 + 0], di * acc[j4 * 4 + 1],
                               di * acc[j4 * 4 + 2], di * acc[j4 * 4 + 3]);
        h[j4] = v;   // h'
        a[j4] = v;   // self-loop contribution (ew = 1)
    }
}

// --------------------------- scatters (HID=16) -----------------------------
// agg[c] += ew * h'[r], 2 edges per thread.

__device__ __forceinline__ void scatter16_edge(const float* __restrict__ h,
                                               float* __restrict__ agg,
                                               int r, int c, float w) {
    const float4* hr = (const float4*)(h + r * HID);
    float4* dst = (float4*)(agg + c * HID);
    float4 v0 = hr[0], v1 = hr[1], v2 = hr[2], v3 = hr[3];
    atomicAdd(dst + 0, make_float4(w * v0.x, w * v0.y, w * v0.z, w * v0.w));
    atomicAdd(dst + 1, make_float4(w * v1.x, w * v1.y, w * v1.z, w * v1.w));
    atomicAdd(dst + 2, make_float4(w * v2.x, w * v2.y, w * v2.z, w * v2.w));
    atomicAdd(dst + 3, make_float4(w * v3.x, w * v3.y, w * v3.z, w * v3.w));
}

__global__ void k_scatter16_l1(const int* __restrict__ ei,
                               const float* __restrict__ ew) {
    int t = blockIdx.x * TPB + threadIdx.x;
    int e = t * 2;
    if (e >= NE) return;
    int2   rr = *(const int2*)(ei + e);
    int2   cc = *(const int2*)(ei + NE + e);
    float2 wwv = *(const float2*)(ew + e);
    scatter16_edge(g_h1, g_agg1, clampN(rr.x), clampN(cc.x), wwv.x);
    scatter16_edge(g_h1, g_agg1, clampN(rr.y), clampN(cc.y), wwv.y);
}

__global__ void k_scatter16_l2(const int* __restrict__ ei,
                               const float* __restrict__ ew) {
    int t = blockIdx.x * TPB + threadIdx.x;
    int e = t * 2;
    if (e >= NE) return;
    int2   rr = *(const int2*)(ei + e);
    int2   cc = *(const int2*)(ei + NE + e);
    float2 wwv = *(const float2*)(ew + e);
    scatter16_edge(g_h2, g_agg2, clampN(rr.x), clampN(cc.x), wwv.x);
    scatter16_edge(g_h2, g_agg2, clampN(rr.y), clampN(cc.y), wwv.y);
}

// ------ finalize layer1: v = relu(dinv*agg1 + b1); h2' = dinv*(v@W3) -------

__global__ void k_fin1_gemm2(const float* __restrict__ b1,
                             const float* __restrict__ W3) {
    __shared__ float Ws[HID * HID];
    __shared__ float bs[HID];
    for (int t = threadIdx.x; t < HID * HID; t += TPB) Ws[t] = W3[t];
    if (threadIdx.x < HID) bs[threadIdx.x] = b1[threadIdx.x];
    __syncthreads();

    int i = blockIdx.x * TPB + threadIdx.x;
    if (i >= NN) return;

    float di = g_dinv[i];
    float v[HID];
    const float4* ar = (const float4*)(g_agg1 + i * HID);
#pragma unroll
    for (int j4 = 0; j4 < HID / 4; j4++) {
        float4 a = ar[j4];
        v[j4 * 4 + 0] = fmaxf(di * a.x + bs[j4 * 4 + 0], 0.0f);
        v[j4 * 4 + 1] = fmaxf(di * a.y + bs[j4 * 4 + 1], 0.0f);
        v[j4 * 4 + 2] = fmaxf(di * a.z + bs[j4 * 4 + 2], 0.0f);
        v[j4 * 4 + 3] = fmaxf(di * a.w + bs[j4 * 4 + 3], 0.0f);
    }

    float acc[HID];
#pragma unroll
    for (int j = 0; j < HID; j++) acc[j] = 0.0f;
#pragma unroll
    for (int k = 0; k < HID; k++) {
        float vk = v[k];
#pragma unroll
        for (int j = 0; j < HID; j++) acc[j] += vk * Ws[k * HID + j];
    }

    float4* h = (float4*)(g_h2 + i * HID);
    float4* a = (float4*)(g_agg2 + i * HID);
#pragma unroll
    for (int j4 = 0; j4 < HID / 4; j4++) {
        float4 w = make_float4(di * acc[j4 * 4 + 0], di * acc[j4 * 4 + 1],
                               di * acc[j4 * 4 + 2], di * acc[j4 * 4 + 3]);
        h[j4] = w;
        a[j4] = w;
    }
}

// ------ finalize layer2: v = relu(dinv*agg2 + b3); h3' = dinv*(v@W2) -------

__global__ void k_fin2_gemm3(const float* __restrict__ b3,
                             const float* __restrict__ W2) {
    __shared__ float Ws[HID * NC];
    __shared__ float bs[HID];
    for (int t = threadIdx.x; t < HID * NC; t += TPB) Ws[t] = W2[t];
    if (threadIdx.x < HID) bs[threadIdx.x] = b3[threadIdx.x];
    __syncthreads();

    int i = blockIdx.x * TPB + threadIdx.x;
    if (i >= NN) return;

    float di = g_dinv[i];
    float v[HID];
    const float4* ar = (const float4*)(g_agg2 + i * HID);
#pragma unroll
    for (int j4 = 0; j4 < HID / 4; j4++) {
        float4 a = ar[j4];
        v[j4 * 4 + 0] = fmaxf(di * a.x + bs[j4 * 4 + 0], 0.0f);
        v[j4 * 4 + 1] = fmaxf(di * a.y + bs[j4 * 4 + 1], 0.0f);
        v[j4 * 4 + 2] = fmaxf(di * a.z + bs[j4 * 4 + 2], 0.0f);
        v[j4 * 4 + 3] = fmaxf(di * a.w + bs[j4 * 4 + 3], 0.0f);
    }

    float acc[NC] = {0.0f, 0.0f, 0.0f, 0.0f};
#pragma unroll
    for (int k = 0; k < HID; k++) {
        float vk = v[k];
#pragma unroll
        for (int j = 0; j < NC; j++) acc[j] += vk * Ws[k * NC + j];
    }

    float4 w = make_float4(di * acc[0], di * acc[1], di * acc[2], di * acc[3]);
    ((float4*)(g_h3 + i * NC))[0] = w;
    ((float4*)(g_agg3 + i * NC))[0] = w;
}

// --------------------------- scatter (NC=4) --------------------------------

__global__ void k_scatter4(const int* __restrict__ ei,
                           const float* __restrict__ ew) {
    int t = blockIdx.x * TPB + threadIdx.x;
    int e = t * 2;
    if (e >= NE) return;
    int2   rr = *(const int2*)(ei + e);
    int2   cc = *(const int2*)(ei + NE + e);
    float2 wwv = *(const float2*)(ew + e);

    float4 v0 = ((const float4*)(g_h3 + clampN(rr.x) * NC))[0];
    float4 v1 = ((const float4*)(g_h3 + clampN(rr.y) * NC))[0];
    atomicAdd((float4*)(g_agg3 + clampN(cc.x) * NC),
              make_float4(wwv.x * v0.x, wwv.x * v0.y, wwv.x * v0.z, wwv.x * v0.w));
    atomicAdd((float4*)(g_agg3 + clampN(cc.y) * NC),
              make_float4(wwv.y * v1.x, wwv.y * v1.y, wwv.y * v1.z, wwv.y * v1.w));
}

// --------------------------- bias + log_softmax ----------------------------

__global__ void k_logsoftmax(const float* __restrict__ b2,
                             float* __restrict__ out) {
    int i = blockIdx.x * TPB + threadIdx.x;
    if (i >= NN) return;
    float di = g_dinv[i];
    float4 a = ((const float4*)(g_agg3 + i * NC))[0];
    float z0 = di * a.x + b2[0];
    float z1 = di * a.y + b2[1];
    float z2 = di * a.z + b2[2];
    float z3 = di * a.w + b2[3];
    float m = fmaxf(fmaxf(z0, z1), fmaxf(z2, z3));
    float s = expf(z0 - m) + expf(z1 - m) + expf(z2 - m) + expf(z3 - m);
    float lse = m + logf(s);
    ((float4*)(out + i * NC))[0] =
        make_float4(z0 - lse, z1 - lse, z2 - lse, z3 - lse);
}

// ---------------------------------------------------------------------------

extern "C" void kernel_launch(void* const* d_in, const int* in_sizes, int n_in,
                              void* d_out, int out_size) {
    const float* x  = (const float*)d_in[0];
    const int*   ei = (const int*)d_in[1];
    const float* ew = (const float*)d_in[2];
    const float* W1 = (const float*)d_in[3];
    const float* b1 = (const float*)d_in[4];
    const float* W3 = (const float*)d_in[5];
    const float* b3 = (const float*)d_in[6];
    const float* W2 = (const float*)d_in[7];
    const float* b2 = (const float*)d_in[8];
    float* out = (float*)d_out;

    const int nbN  = (NN + TPB - 1) / TPB;
    const int nbE2 = (NE / 2 + TPB - 1) / TPB;

    k_init_deg<<<nbN, TPB>>>();
    k_deg<<<nbE2, TPB>>>(ei, ew);
    k_rsqrt<<<nbN, TPB>>>();

    k_gemm1<<<nbN, TPB>>>(x, W1);
    k_scatter16_l1<<<nbE2, TPB>>>(ei, ew);

    k_fin1_gemm2<<<nbN, TPB>>>(b1, W3);
    k_scatter16_l2<<<nbE2, TPB>>>(ei, ew);

    k_fin2_gemm3<<<nbN, TPB>>>(b3, W2);
    k_scatter4<<<nbE2, TPB>>>(ei, ew);

    k_logsoftmax<<<nbN, TPB>>>(b2, out);
}

// round 8
// speedup vs baseline: 1.3229x; 1.1771x over previous
#include <cuda_runtime.h>

// ---------------------------------------------------------------------------
// 3-layer GCN, R8: CSR-based aggregation (no atomics in hot path).
//  prep: count in-degree -> block scan -> fill CSR {row, w} -> deg/dinv from CSR
//  layers: h' = dinv*(v@W); agg[c] = h'[c] + sum_in ew*h'[row]; v = relu(dinv*agg+b)
//  (norm factored: norm*h[row] = dinv[col]*ew*(dinv[row]*h[row]))
// ---------------------------------------------------------------------------

#define NN 100000
#define NE 3200000
#define FIN 64
#define HID 16
#define NC 4
#define TPB 256
#define SCANB 1024
#define NSCAN ((NN + SCANB - 1) / SCANB)   // 98

__device__ float g_dinv[NN];
__device__ int   g_cnt[NN];
__device__ int   g_ptr[NN];
__device__ int   g_fill[NN];
__device__ int   g_bsum[128];
__device__ int   g_boff[128];
__device__ __align__(16) int2  g_csr[NE];        // {row, weight-as-int}
__device__ __align__(16) float g_h1[NN * HID];
__device__ __align__(16) float g_agg1[NN * HID];
__device__ __align__(16) float g_h2[NN * HID];
__device__ __align__(16) float g_agg2[NN * HID];
__device__ __align__(16) float g_h3[NN * NC];
__device__ __align__(16) float g_agg3[NN * NC];

__device__ __forceinline__ int clampN(int v) {
    v = v < 0 ? 0 : v;
    return v >= NN ? NN - 1 : v;
}

// --------------------------- CSR build -------------------------------------

__global__ void k_zero_cnt() {
    int i = blockIdx.x * TPB + threadIdx.x;
    if (i < NN) g_cnt[i] = 0;
}

__global__ void k_cnt(const int* __restrict__ ei) {
    int t = blockIdx.x * TPB + threadIdx.x;
    int e = t * 2;
    if (e >= NE) return;
    int2 cc = *(const int2*)(ei + NE + e);
    atomicAdd(&g_cnt[clampN(cc.x)], 1);
    atomicAdd(&g_cnt[clampN(cc.y)], 1);
}

__global__ void k_scan1() {
    __shared__ int s[SCANB];
    int tid = threadIdx.x;
    int i = blockIdx.x * SCANB + tid;
    int v = (i < NN) ? g_cnt[i] : 0;
    s[tid] = v;
    __syncthreads();
#pragma unroll
    for (int off = 1; off < SCANB; off <<= 1) {
        int t = (tid >= off) ? s[tid - off] : 0;
        __syncthreads();
        s[tid] += t;
        __syncthreads();
    }
    if (i < NN) g_ptr[i] = s[tid] - v;            // exclusive (block-local)
    if (tid == SCANB - 1) g_bsum[blockIdx.x] = s[tid];
}

__global__ void k_scan2() {
    __shared__ int s[128];
    int tid = threadIdx.x;
    int v = (tid < NSCAN) ? g_bsum[tid] : 0;
    s[tid] = v;
    __syncthreads();
#pragma unroll
    for (int off = 1; off < 128; off <<= 1) {
        int t = (tid >= off) ? s[tid - off] : 0;
        __syncthreads();
        s[tid] += t;
        __syncthreads();
    }
    g_boff[tid] = s[tid] - v;                     // exclusive block offsets
}

__global__ void k_ptr_fin() {
    int i = blockIdx.x * TPB + threadIdx.x;
    if (i >= NN) return;
    int p = g_ptr[i] + g_boff[i >> 10];
    g_ptr[i] = p;
    g_fill[i] = p;
}

__global__ void k_fill(const int* __restrict__ ei, const float* __restrict__ ew) {
    int t = blockIdx.x * TPB + threadIdx.x;
    int e = t * 2;
    if (e >= NE) return;
    int2   rr = *(const int2*)(ei + e);
    int2   cc = *(const int2*)(ei + NE + e);
    float2 ww = *(const float2*)(ew + e);
    int s0 = atomicAdd(&g_fill[clampN(cc.x)], 1);
    g_csr[s0] = make_int2(clampN(rr.x), __float_as_int(ww.x));
    int s1 = atomicAdd(&g_fill[clampN(cc.y)], 1);
    g_csr[s1] = make_int2(clampN(rr.y), __float_as_int(ww.y));
}

// deg[i] = 1 + sum of CSR weights of node i; dinv = rsqrt(deg). Warp per node.
__global__ void k_dinv() {
    int w = blockIdx.x * (TPB / 32) + (threadIdx.x >> 5);
    if (w >= NN) return;
    int lane = threadIdx.x & 31;
    int base = g_ptr[w];
    int cnt  = g_cnt[w];
    float s = 0.0f;
    for (int k = lane; k < cnt; k += 32)
        s += __int_as_float(g_csr[base + k].y);
#pragma unroll
    for (int o = 16; o > 0; o >>= 1) s += __shfl_xor_sync(0xffffffffu, s, o);
    if (lane == 0) g_dinv[w] = rsqrtf(s + 1.0f);  // +1 self-loop; deg > 0 always
}

// ------------------- layer 1: h1' = dinv*(x@W1); agg1 = h1' ----------------
// 2 threads per node; each covers 32 of the 64 K-elements, one shfl round.

__global__ void k_gemm1(const float* __restrict__ x,
                        const float* __restrict__ W1) {
    __shared__ float Ws[FIN * HID];
    for (int t = threadIdx.x; t < FIN * HID; t += TPB) Ws[t] = W1[t];
    __syncthreads();

    int t = blockIdx.x * TPB + threadIdx.x;
    int node = t >> 1;
    int half = t & 1;
    if (node >= NN) return;

    float acc[HID];
#pragma unroll
    for (int j = 0; j < HID; j++) acc[j] = 0.0f;

    const float4* xr = (const float4*)(x + (size_t)node * FIN) + half * 8;
#pragma unroll
    for (int b = 0; b < 2; b++) {                 // 2 batches of 4 loads (MLP=4)
        float4 xv0 = xr[b * 4 + 0];
        float4 xv1 = xr[b * 4 + 1];
        float4 xv2 = xr[b * 4 + 2];
        float4 xv3 = xr[b * 4 + 3];
        int kb = half * 32 + b * 16;
#pragma unroll
        for (int j = 0; j < HID; j++) {
            acc[j] += xv0.x * Ws[(kb +  0) * HID + j] + xv0.y * Ws[(kb +  1) * HID + j]
                    + xv0.z * Ws[(kb +  2) * HID + j] + xv0.w * Ws[(kb +  3) * HID + j];
            acc[j] += xv1.x * Ws[(kb +  4) * HID + j] + xv1.y * Ws[(kb +  5) * HID + j]
                    + xv1.z * Ws[(kb +  6) * HID + j] + xv1.w * Ws[(kb +  7) * HID + j];
            acc[j] += xv2.x * Ws[(kb +  8) * HID + j] + xv2.y * Ws[(kb +  9) * HID + j]
                    + xv2.z * Ws[(kb + 10) * HID + j] + xv2.w * Ws[(kb + 11) * HID + j];
            acc[j] += xv3.x * Ws[(kb + 12) * HID + j] + xv3.y * Ws[(kb + 13) * HID + j]
                    + xv3.z * Ws[(kb + 14) * HID + j] + xv3.w * Ws[(kb + 15) * HID + j];
        }
    }

    // butterfly: half 0 keeps features 0..7, half 1 keeps 8..15
    float r[8];
#pragma unroll
    for (int j = 0; j < 8; j++) {
        float sendv = half ? acc[j] : acc[j + 8];
        float recv  = __shfl_xor_sync(0xffffffffu, sendv, 1);
        float keep  = half ? acc[j + 8] : acc[j];
        r[j] = keep + recv;
    }

    float di = g_dinv[node];
    int fb = half * 8;
    float4 v0 = make_float4(di * r[0], di * r[1], di * r[2], di * r[3]);
    float4 v1 = make_float4(di * r[4], di * r[5], di * r[6], di * r[7]);
    float4* h = (float4*)(g_h1 + node * HID + fb);
    float4* a = (float4*)(g_agg1 + node * HID + fb);
    h[0] = v0; h[1] = v1;
    a[0] = v0; a[1] = v1;                         // self-loop contribution
}

// ---------------- CSR aggregation, HID=16: warp per node -------------------
// lanes: f = lane&15 (feature), sub = lane>>4 (edge-parity). Gathers are
// coalesced 64B lines; single plain read-modify-write of agg at the end.

#define AGG16_BODY(H, AGG)                                                    \
    int w = blockIdx.x * (TPB / 32) + (threadIdx.x >> 5);                     \
    if (w >= NN) return;                                                      \
    int lane = threadIdx.x & 31;                                              \
    int f = lane & 15, sub = lane >> 4;                                       \
    int base = g_ptr[w];                                                      \
    int cnt  = g_cnt[w];                                                      \
    float acc = 0.0f;                                                         \
    int k = sub;                                                              \
    for (; k + 2 < cnt; k += 4) {                                             \
        int2 ra = g_csr[base + k];                                            \
        int2 rb = g_csr[base + k + 2];                                        \
        float ha = (H)[ra.x * HID + f];                                       \
        float hb = (H)[rb.x * HID + f];                                       \
        acc += __int_as_float(ra.y) * ha;                                     \
        acc += __int_as_float(rb.y) * hb;                                     \
    }                                                                         \
    for (; k < cnt; k += 2) {                                                 \
        int2 rc = g_csr[base + k];                                            \
        acc += __int_as_float(rc.y) * (H)[rc.x * HID + f];                    \
    }                                                                         \
    acc += __shfl_xor_sync(0xffffffffu, acc, 16);                             \
    if (sub == 0) (AGG)[w * HID + f] += acc;

__global__ void k_agg16_l1() { AGG16_BODY(g_h1, g_agg1) }
__global__ void k_agg16_l2() { AGG16_BODY(g_h2, g_agg2) }

// ------ finalize layer1: v = relu(dinv*agg1 + b1); h2' = dinv*(v@W3) -------

__global__ void k_fin1_gemm2(const float* __restrict__ b1,
                             const float* __restrict__ W3) {
    __shared__ float Ws[HID * HID];
    __shared__ float bs[HID];
    for (int t = threadIdx.x; t < HID * HID; t += TPB) Ws[t] = W3[t];
    if (threadIdx.x < HID) bs[threadIdx.x] = b1[threadIdx.x];
    __syncthreads();

    int i = blockIdx.x * TPB + threadIdx.x;
    if (i >= NN) return;

    float di = g_dinv[i];
    float v[HID];
    const float4* ar = (const float4*)(g_agg1 + i * HID);
#pragma unroll
    for (int j4 = 0; j4 < HID / 4; j4++) {
        float4 a = ar[j4];
        v[j4 * 4 + 0] = fmaxf(di * a.x + bs[j4 * 4 + 0], 0.0f);
        v[j4 * 4 + 1] = fmaxf(di * a.y + bs[j4 * 4 + 1], 0.0f);
        v[j4 * 4 + 2] = fmaxf(di * a.z + bs[j4 * 4 + 2], 0.0f);
        v[j4 * 4 + 3] = fmaxf(di * a.w + bs[j4 * 4 + 3], 0.0f);
    }

    float acc[HID];
#pragma unroll
    for (int j = 0; j < HID; j++) acc[j] = 0.0f;
#pragma unroll
    for (int k = 0; k < HID; k++) {
        float vk = v[k];
#pragma unroll
        for (int j = 0; j < HID; j++) acc[j] += vk * Ws[k * HID + j];
    }

    float4* h = (float4*)(g_h2 + i * HID);
    float4* a = (float4*)(g_agg2 + i * HID);
#pragma unroll
    for (int j4 = 0; j4 < HID / 4; j4++) {
        float4 wv = make_float4(di * acc[j4 * 4 + 0], di * acc[j4 * 4 + 1],
                                di * acc[j4 * 4 + 2], di * acc[j4 * 4 + 3]);
        h[j4] = wv;
        a[j4] = wv;
    }
}

// ------ finalize layer2: v = relu(dinv*agg2 + b3); h3' = dinv*(v@W2) -------

__global__ void k_fin2_gemm3(const float* __restrict__ b3,
                             const float* __restrict__ W2) {
    __shared__ float Ws[HID * NC];
    __shared__ float bs[HID];
    for (int t = threadIdx.x; t < HID * NC; t += TPB) Ws[t] = W2[t];
    if (threadIdx.x < HID) bs[threadIdx.x] = b3[threadIdx.x];
    __syncthreads();

    int i = blockIdx.x * TPB + threadIdx.x;
    if (i >= NN) return;

    float di = g_dinv[i];
    float v[HID];
    const float4* ar = (const float4*)(g_agg2 + i * HID);
#pragma unroll
    for (int j4 = 0; j4 < HID / 4; j4++) {
        float4 a = ar[j4];
        v[j4 * 4 + 0] = fmaxf(di * a.x + bs[j4 * 4 + 0], 0.0f);
        v[j4 * 4 + 1] = fmaxf(di * a.y + bs[j4 * 4 + 1], 0.0f);
        v[j4 * 4 + 2] = fmaxf(di * a.z + bs[j4 * 4 + 2], 0.0f);
        v[j4 * 4 + 3] = fmaxf(di * a.w + bs[j4 * 4 + 3], 0.0f);
    }

    float acc[NC] = {0.0f, 0.0f, 0.0f, 0.0f};
#pragma unroll
    for (int k = 0; k < HID; k++) {
        float vk = v[k];
#pragma unroll
        for (int j = 0; j < NC; j++) acc[j] += vk * Ws[k * NC + j];
    }

    float4 wv = make_float4(di * acc[0], di * acc[1], di * acc[2], di * acc[3]);
    ((float4*)(g_h3 + i * NC))[0] = wv;
    ((float4*)(g_agg3 + i * NC))[0] = wv;
}

// ---------------- CSR aggregation, NC=4: warp per node ---------------------

__global__ void k_agg4_l3() {
    int w = blockIdx.x * (TPB / 32) + (threadIdx.x >> 5);
    if (w >= NN) return;
    int lane = threadIdx.x & 31;
    int f = lane & 3, sub = lane >> 2;            // 8 edge-slots per iter
    int base = g_ptr[w];
    int cnt  = g_cnt[w];
    float acc = 0.0f;
    for (int k = sub; k < cnt; k += 8) {
        int2 rc = g_csr[base + k];
        acc += __int_as_float(rc.y) * g_h3[rc.x * NC + f];
    }
    acc += __shfl_xor_sync(0xffffffffu, acc, 4);
    acc += __shfl_xor_sync(0xffffffffu, acc, 8);
    acc += __shfl_xor_sync(0xffffffffu, acc, 16);
    if (sub == 0) g_agg3[w * NC + f] += acc;
}

// --------------------------- bias + log_softmax ----------------------------

__global__ void k_logsoftmax(const float* __restrict__ b2,
                             float* __restrict__ out) {
    int i = blockIdx.x * TPB + threadIdx.x;
    if (i >= NN) return;
    float di = g_dinv[i];
    float4 a = ((const float4*)(g_agg3 + i * NC))[0];
    float z0 = di * a.x + b2[0];
    float z1 = di * a.y + b2[1];
    float z2 = di * a.z + b2[2];
    float z3 = di * a.w + b2[3];
    float m = fmaxf(fmaxf(z0, z1), fmaxf(z2, z3));
    float s = expf(z0 - m) + expf(z1 - m) + expf(z2 - m) + expf(z3 - m);
    float lse = m + logf(s);
    ((float4*)(out + i * NC))[0] =
        make_float4(z0 - lse, z1 - lse, z2 - lse, z3 - lse);
}

// ---------------------------------------------------------------------------

extern "C" void kernel_launch(void* const* d_in, const int* in_sizes, int n_in,
                              void* d_out, int out_size) {
    const float* x  = (const float*)d_in[0];
    const int*   ei = (const int*)d_in[1];
    const float* ew = (const float*)d_in[2];
    const float* W1 = (const float*)d_in[3];
    const float* b1 = (const float*)d_in[4];
    const float* W3 = (const float*)d_in[5];
    const float* b3 = (const float*)d_in[6];
    const float* W2 = (const float*)d_in[7];
    const float* b2 = (const float*)d_in[8];
    float* out = (float*)d_out;

    const int nbN  = (NN + TPB - 1) / TPB;
    const int nbN2 = (NN * 2 + TPB - 1) / TPB;            // gemm1: 2 thr/node
    const int nbE2 = (NE / 2 + TPB - 1) / TPB;            // 2 edges/thread
    const int nbW  = (NN + (TPB / 32) - 1) / (TPB / 32);  // warp/node kernels

    // CSR build
    k_zero_cnt<<<nbN, TPB>>>();
    k_cnt<<<nbE2, TPB>>>(ei);
    k_scan1<<<NSCAN, SCANB>>>();
    k_scan2<<<1, 128>>>();
    k_ptr_fin<<<nbN, TPB>>>();
    k_fill<<<nbE2, TPB>>>(ei, ew);
    k_dinv<<<nbW, TPB>>>();

    // layers
    k_gemm1<<<nbN2, TPB>>>(x, W1);
    k_agg16_l1<<<nbW, TPB>>>();
    k_fin1_gemm2<<<nbN, TPB>>>(b1, W3);
    k_agg16_l2<<<nbW, TPB>>>();
    k_fin2_gemm3<<<nbN, TPB>>>(b3, W2);
    k_agg4_l3<<<nbW, TPB>>>();
    k_logsoftmax<<<nbN, TPB>>>(b2, out);
}